// round 2
// baseline (speedup 1.0000x reference)
#include <cuda_runtime.h>
#include <cuda_fp16.h>
#include <cstdint>

// ============================================================================
// MQA_22436909154690 on GB300 (sm_103 base target -- NO tcgen05 available,
// the harness compiles PTX at .target sm_103 without the 'a' feature suffix).
//
// Math: softmax in the reference is over a singleton axis -> identically 1.
//   out[b,l] = tile(v[b,l], H),   v = x @ Wv^T + bv,   Wv = Wkv[HD:2HD, :]
// Single GEMM [16384 x 2048] @ [2048 x 128] + bias + broadcast-x16 epilogue.
//
// Tensor path: mma.sync.m16n8k16 fp16 (f32 accum). fp16 single-pass rel err
// ~3e-4 (11-bit mantissa, K-independent relative error) < 1e-3 threshold.
// ============================================================================

static constexpr int KDIM  = 2048;
static constexpr int MTILE = 128;
static constexpr int KC    = 64;            // K columns per chunk
static constexpr int NCH   = KDIM / KC;     // 32 chunks

// SMEM layout (bytes). A/B tiles padded to 72 halves/row (144B) so ldmatrix
// row addresses land on distinct bank quads (36 words/row, 4r mod 32 pattern).
static constexpr int SA  = 0;               // A: [128][72] half = 18432 B
static constexpr int SB0 = 18432;           // B buf0: [128][72] half
static constexpr int SB1 = 36864;           // B buf1
static constexpr int SMEM_TOTAL = 128 * 132 * 4;  // 67584 (epilogue v overlay)
static constexpr int V_STRIDE = 132;

// Pre-converted Wv in fp16, chunk-major: [chunk][n=128][k=64]
__device__ __align__(16) __half g_Wh[NCH * 128 * KC];

// ---------------------------------------------------------------------------
__device__ __forceinline__ uint32_t smem_u32(const void* p) {
    uint32_t a;
    asm("{ .reg .u64 t; cvta.to.shared.u64 t, %1; cvt.u32.u64 %0, t; }" : "=r"(a) : "l"(p));
    return a;
}
__device__ __forceinline__ void ldsm4(uint32_t* r, uint32_t addr) {
    asm volatile("ldmatrix.sync.aligned.m8n8.x4.shared.b16 {%0,%1,%2,%3}, [%4];"
                 : "=r"(r[0]), "=r"(r[1]), "=r"(r[2]), "=r"(r[3]) : "r"(addr));
}
__device__ __forceinline__ void hmma(float* d, const uint32_t* a, uint32_t b0, uint32_t b1) {
    asm volatile("mma.sync.aligned.m16n8k16.row.col.f32.f16.f16.f32 "
                 "{%0,%1,%2,%3}, {%4,%5,%6,%7}, {%8,%9}, {%0,%1,%2,%3};"
                 : "+f"(d[0]), "+f"(d[1]), "+f"(d[2]), "+f"(d[3])
                 : "r"(a[0]), "r"(a[1]), "r"(a[2]), "r"(a[3]), "r"(b0), "r"(b1));
}
template <int N>
__device__ __forceinline__ void cpwait() {
    asm volatile("cp.async.wait_group %0;" :: "n"(N) : "memory");
}
__device__ __forceinline__ uint32_t h2u(__half2 h) { return *reinterpret_cast<uint32_t*>(&h); }

// ---------------------------------------------------------------------------
// Pre-kernel: Wv = Wkv rows 128..255 -> fp16, chunk-major layout for cp.async.
// ---------------------------------------------------------------------------
__global__ void convert_w_kernel(const float* __restrict__ Wkv) {
    int idx = blockIdx.x * blockDim.x + threadIdx.x;  // 65536 threads, 4 halves
    int h4 = idx << 2;
    int c  = h4 >> 13;            // chunk
    int n  = (h4 >> 6) & 127;     // output column
    int k4 = h4 & 63;             // k within chunk
    float4 w = *(const float4*)(Wkv + (size_t)(128 + n) * KDIM + c * KC + k4);
    __half2 p0 = __float22half2_rn(make_float2(w.x, w.y));
    __half2 p1 = __float22half2_rn(make_float2(w.z, w.w));
    *(uint2*)(g_Wh + h4) = make_uint2(h2u(p0), h2u(p1));
}

// ---------------------------------------------------------------------------
// Main kernel: 128 CTAs x 256 threads. 8 warps as 2(M) x 4(N).
// ---------------------------------------------------------------------------
__global__ void __launch_bounds__(256, 1)
mqa_gemm_kernel(const float* __restrict__ x, const float* __restrict__ bkv,
                float* __restrict__ out) {
    extern __shared__ char smem[];
    const uint32_t sb = smem_u32(smem);
    const int tid    = threadIdx.x;
    const int wid    = tid >> 5;
    const int lane   = tid & 31;
    const int warp_m = wid >> 2;   // 0..1
    const int warp_n = wid & 3;    // 0..3

    const float* xb = x + (size_t)blockIdx.x * MTILE * KDIM;

    // ldmatrix base addresses (byte offsets into A / B tiles)
    uint32_t aAddr[4];
    #pragma unroll
    for (int mf = 0; mf < 4; ++mf)
        aAddr[mf] = sb + SA + (((warp_m * 64 + mf * 16 + (lane & 15)) * 72) << 1)
                  + ((lane >> 4) << 4);
    uint32_t bOff[2];
    #pragma unroll
    for (int g = 0; g < 2; ++g)
        bOff[g] = (((warp_n * 32 + g * 16 + (lane & 15)) * 72) << 1) + ((lane >> 4) << 4);

    float acc[4][4][4];
    #pragma unroll
    for (int mf = 0; mf < 4; ++mf)
        #pragma unroll
        for (int nf = 0; nf < 4; ++nf)
            #pragma unroll
            for (int r = 0; r < 4; ++r) acc[mf][nf][r] = 0.f;

    float4 xs[4][2];

    // --- helpers (lambdas keep register lifetimes tight) ---
    auto ldx = [&](int ch) {
        #pragma unroll
        for (int i = 0; i < 4; ++i) {
            int f8 = tid + i * 256;                         // 8-float unit index
            const float* p = xb + (size_t)(f8 >> 3) * KDIM + ch * KC + ((f8 & 7) << 3);
            xs[i][0] = ((const float4*)p)[0];
            xs[i][1] = ((const float4*)p)[1];
        }
    };
    auto stx = [&]() {
        #pragma unroll
        for (int i = 0; i < 4; ++i) {
            int f8 = tid + i * 256;
            __half2 h0 = __float22half2_rn(make_float2(xs[i][0].x, xs[i][0].y));
            __half2 h1 = __float22half2_rn(make_float2(xs[i][0].z, xs[i][0].w));
            __half2 h2 = __float22half2_rn(make_float2(xs[i][1].x, xs[i][1].y));
            __half2 h3 = __float22half2_rn(make_float2(xs[i][1].z, xs[i][1].w));
            uint4 v = make_uint4(h2u(h0), h2u(h1), h2u(h2), h2u(h3));
            *(uint4*)(smem + SA + (((f8 >> 3) * 72 + ((f8 & 7) << 3)) << 1)) = v;
        }
    };
    auto cpB = [&](int ch, int buf) {
        const __half* src = g_Wh + (size_t)ch * (128 * KC);
        uint32_t dbase = sb + (buf ? SB1 : SB0);
        #pragma unroll
        for (int j = 0; j < 4; ++j) {
            int idx = tid + j * 256;
            int n = idx >> 3, seg = idx & 7;
            uint32_t dst = dbase + ((n * 72 + seg * 8) << 1);
            const void* s = src + n * KC + seg * 8;
            asm volatile("cp.async.cg.shared.global [%0], [%1], 16;"
                         :: "r"(dst), "l"(s) : "memory");
        }
        asm volatile("cp.async.commit_group;" ::: "memory");
    };
    auto mmaChunk = [&](int buf) {
        uint32_t bB = sb + (buf ? SB1 : SB0);
        #pragma unroll
        for (int kk = 0; kk < 4; ++kk) {
            uint32_t a[4][4];
            #pragma unroll
            for (int mf = 0; mf < 4; ++mf) ldsm4(a[mf], aAddr[mf] + kk * 32);
            uint32_t b[2][4];
            ldsm4(b[0], bB + bOff[0] + kk * 32);
            ldsm4(b[1], bB + bOff[1] + kk * 32);
            #pragma unroll
            for (int mf = 0; mf < 4; ++mf) {
                hmma(acc[mf][0], a[mf], b[0][0], b[0][2]);
                hmma(acc[mf][1], a[mf], b[0][1], b[0][3]);
                hmma(acc[mf][2], a[mf], b[1][0], b[1][2]);
                hmma(acc[mf][3], a[mf], b[1][1], b[1][3]);
            }
        }
    };

    // --- prologue ---
    cpB(0, 0);
    cpB(1, 1);
    ldx(0);
    stx();
    cpwait<1>();          // B chunk 0 resident
    __syncthreads();      // A chunk 0 + B chunk 0 visible

    // --- main loop ---
    for (int it = 0; it < NCH; ++it) {
        if (it + 1 < NCH) ldx(it + 1);      // issue LDGs early (hidden by mma)
        mmaChunk(it & 1);
        __syncthreads();                     // all reads of A / B[it] done
        if (it + 1 < NCH) {
            stx();                           // A <- chunk it+1
            if (it + 2 < NCH) { cpB(it + 2, it & 1); cpwait<1>(); }
            else              { cpwait<0>(); }
            __syncthreads();                 // A + B[it+1] visible
        }
    }

    // --- epilogue: bias from gmem (L2-hot), v tile to SMEM, broadcast x16 ---
    float bias[4][2];
    {
        int c0 = warp_n * 32 + (lane & 3) * 2;
        #pragma unroll
        for (int nf = 0; nf < 4; ++nf) {
            bias[nf][0] = bkv[128 + c0 + nf * 8];
            bias[nf][1] = bkv[129 + c0 + nf * 8];
        }
    }
    __syncthreads();                         // everyone done with mainloop smem

    float* vsm = (float*)smem;
    {
        int r0 = warp_m * 64 + (lane >> 2);
        #pragma unroll
        for (int mf = 0; mf < 4; ++mf) {
            #pragma unroll
            for (int nf = 0; nf < 4; ++nf) {
                int r = r0 + mf * 16;
                int c = warp_n * 32 + nf * 8 + (lane & 3) * 2;
                vsm[r * V_STRIDE + c]           = acc[mf][nf][0] + bias[nf][0];
                vsm[r * V_STRIDE + c + 1]       = acc[mf][nf][1] + bias[nf][1];
                vsm[(r + 8) * V_STRIDE + c]     = acc[mf][nf][2] + bias[nf][0];
                vsm[(r + 8) * V_STRIDE + c + 1] = acc[mf][nf][3] + bias[nf][1];
            }
        }
    }
    __syncthreads();

    float* ob = out + (size_t)blockIdx.x * MTILE * 2048;
    for (int r = wid; r < 128; r += 8) {
        float4 val = *(const float4*)(vsm + r * V_STRIDE + lane * 4);
        float4* orow = (float4*)(ob + (size_t)r * 2048);
        #pragma unroll
        for (int h = 0; h < 16; ++h) orow[lane + h * 32] = val;
    }
}

// ---------------------------------------------------------------------------
extern "C" void kernel_launch(void* const* d_in, const int* in_sizes, int n_in,
                              void* d_out, int out_size) {
    const float* x   = (const float*)d_in[0];   // (4,4096,2048) fp32
    const float* Wkv = (const float*)d_in[3];   // (256,2048) fp32
    const float* bkv = (const float*)d_in[4];   // (256,) fp32
    float* out = (float*)d_out;                 // (4,4096,2048) fp32

    cudaFuncSetAttribute(mqa_gemm_kernel,
                         cudaFuncAttributeMaxDynamicSharedMemorySize, SMEM_TOTAL);

    convert_w_kernel<<<256, 256>>>(Wkv);
    mqa_gemm_kernel<<<16384 / MTILE, 256, SMEM_TOTAL>>>(x, bkv, out);
}

// round 3
// speedup vs baseline: 1.0248x; 1.0248x over previous
#include <cuda_runtime.h>
#include <cuda_fp16.h>
#include <cstdint>

// ============================================================================
// MQA_22436909154690 on GB300 (sm_103 base target -- no tcgen05 at this
// PTX target; HMMA mma.sync path).
//
// Math: softmax over singleton axis == 1, so
//   out[b,l] = tile(v[b,l], H),  v = x @ Wv^T + bv,  Wv = Wkv[HD:2HD, :]
// => one GEMM [16384 x 2048] @ [2048 x 128] + bias + broadcast-x16 epilogue.
//
// R3 change vs R2: MTILE 128 -> 64, grid 128 -> 256 CTAs, 2 CTAs/SM
// (__launch_bounds__(256,2)). R2 ncu: DRAM 43%, occ 12.5%, 20 idle SMs ->
// latency-bound. Double the resident warps + fill all SMs.
// ============================================================================

static constexpr int KDIM  = 2048;
static constexpr int MTILE = 64;
static constexpr int KC    = 64;            // K columns per chunk
static constexpr int NCH   = KDIM / KC;     // 32 chunks

// SMEM layout (bytes). Tiles padded to 72 halves/row for conflict-free ldmatrix.
static constexpr int SA  = 0;                       // A: [64][72] half = 9216 B
static constexpr int SB0 = 9216;                    // B buf0: [128][72] half
static constexpr int SB1 = 9216 + 18432;            // B buf1
static constexpr int MAIN_SMEM = SB1 + 18432;       // 46080
static constexpr int V_STRIDE  = 132;
static constexpr int SMEM_TOTAL = MAIN_SMEM;        // > 64*132*4 = 33792 overlay

// Pre-converted Wv in fp16, chunk-major: [chunk][n=128][k=64]
__device__ __align__(16) __half g_Wh[NCH * 128 * KC];

// ---------------------------------------------------------------------------
__device__ __forceinline__ uint32_t smem_u32(const void* p) {
    uint32_t a;
    asm("{ .reg .u64 t; cvta.to.shared.u64 t, %1; cvt.u32.u64 %0, t; }" : "=r"(a) : "l"(p));
    return a;
}
__device__ __forceinline__ void ldsm4(uint32_t* r, uint32_t addr) {
    asm volatile("ldmatrix.sync.aligned.m8n8.x4.shared.b16 {%0,%1,%2,%3}, [%4];"
                 : "=r"(r[0]), "=r"(r[1]), "=r"(r[2]), "=r"(r[3]) : "r"(addr));
}
__device__ __forceinline__ void hmma(float* d, const uint32_t* a, uint32_t b0, uint32_t b1) {
    asm volatile("mma.sync.aligned.m16n8k16.row.col.f32.f16.f16.f32 "
                 "{%0,%1,%2,%3}, {%4,%5,%6,%7}, {%8,%9}, {%0,%1,%2,%3};"
                 : "+f"(d[0]), "+f"(d[1]), "+f"(d[2]), "+f"(d[3])
                 : "r"(a[0]), "r"(a[1]), "r"(a[2]), "r"(a[3]), "r"(b0), "r"(b1));
}
template <int N>
__device__ __forceinline__ void cpwait() {
    asm volatile("cp.async.wait_group %0;" :: "n"(N) : "memory");
}
__device__ __forceinline__ uint32_t h2u(__half2 h) { return *reinterpret_cast<uint32_t*>(&h); }

// ---------------------------------------------------------------------------
// Pre-kernel: Wv = Wkv rows 128..255 -> fp16, chunk-major layout for cp.async.
// ---------------------------------------------------------------------------
__global__ void convert_w_kernel(const float* __restrict__ Wkv) {
    int idx = blockIdx.x * blockDim.x + threadIdx.x;  // 65536 threads, 4 halves
    int h4 = idx << 2;
    int c  = h4 >> 13;            // chunk
    int n  = (h4 >> 6) & 127;     // output column
    int k4 = h4 & 63;             // k within chunk
    float4 w = *(const float4*)(Wkv + (size_t)(128 + n) * KDIM + c * KC + k4);
    __half2 p0 = __float22half2_rn(make_float2(w.x, w.y));
    __half2 p1 = __float22half2_rn(make_float2(w.z, w.w));
    *(uint2*)(g_Wh + h4) = make_uint2(h2u(p0), h2u(p1));
}

// ---------------------------------------------------------------------------
// Main kernel: 256 CTAs x 256 threads, 2 CTAs/SM. 8 warps as 2(M) x 4(N),
// each warp owns a 32x32 fragment of the 64x128 C tile.
// ---------------------------------------------------------------------------
__global__ void __launch_bounds__(256, 2)
mqa_gemm_kernel(const float* __restrict__ x, const float* __restrict__ bkv,
                float* __restrict__ out) {
    extern __shared__ char smem[];
    const uint32_t sb = smem_u32(smem);
    const int tid    = threadIdx.x;
    const int wid    = tid >> 5;
    const int lane   = tid & 31;
    const int warp_m = wid >> 2;   // 0..1 (32 rows each)
    const int warp_n = wid & 3;    // 0..3 (32 cols each)

    const float* xb = x + (size_t)blockIdx.x * MTILE * KDIM;

    // ldmatrix base addresses (byte offsets)
    uint32_t aAddr[2];
    #pragma unroll
    for (int mf = 0; mf < 2; ++mf)
        aAddr[mf] = sb + SA + (((warp_m * 32 + mf * 16 + (lane & 15)) * 72) << 1)
                  + ((lane >> 4) << 4);
    uint32_t bOff[2];
    #pragma unroll
    for (int g = 0; g < 2; ++g)
        bOff[g] = (((warp_n * 32 + g * 16 + (lane & 15)) * 72) << 1) + ((lane >> 4) << 4);

    float acc[2][4][4];
    #pragma unroll
    for (int mf = 0; mf < 2; ++mf)
        #pragma unroll
        for (int nf = 0; nf < 4; ++nf)
            #pragma unroll
            for (int r = 0; r < 4; ++r) acc[mf][nf][r] = 0.f;

    float4 xs[2][2];   // register staging for the next x chunk (64x64 fp32)

    auto ldx = [&](int ch) {
        #pragma unroll
        for (int i = 0; i < 2; ++i) {
            int f8 = tid + i * 256;                         // 8-float unit, 0..511
            const float* p = xb + (size_t)(f8 >> 3) * KDIM + ch * KC + ((f8 & 7) << 3);
            xs[i][0] = ((const float4*)p)[0];
            xs[i][1] = ((const float4*)p)[1];
        }
    };
    auto stx = [&]() {
        #pragma unroll
        for (int i = 0; i < 2; ++i) {
            int f8 = tid + i * 256;
            __half2 h0 = __float22half2_rn(make_float2(xs[i][0].x, xs[i][0].y));
            __half2 h1 = __float22half2_rn(make_float2(xs[i][0].z, xs[i][0].w));
            __half2 h2 = __float22half2_rn(make_float2(xs[i][1].x, xs[i][1].y));
            __half2 h3 = __float22half2_rn(make_float2(xs[i][1].z, xs[i][1].w));
            uint4 v = make_uint4(h2u(h0), h2u(h1), h2u(h2), h2u(h3));
            *(uint4*)(smem + SA + (((f8 >> 3) * 72 + ((f8 & 7) << 3)) << 1)) = v;
        }
    };
    auto cpB = [&](int ch, int buf) {
        const __half* src = g_Wh + (size_t)ch * (128 * KC);
        uint32_t dbase = sb + (buf ? SB1 : SB0);
        #pragma unroll
        for (int j = 0; j < 4; ++j) {
            int idx = tid + j * 256;
            int n = idx >> 3, seg = idx & 7;
            uint32_t dst = dbase + ((n * 72 + seg * 8) << 1);
            const void* s = src + n * KC + seg * 8;
            asm volatile("cp.async.cg.shared.global [%0], [%1], 16;"
                         :: "r"(dst), "l"(s) : "memory");
        }
        asm volatile("cp.async.commit_group;" ::: "memory");
    };
    auto mmaChunk = [&](int buf) {
        uint32_t bB = sb + (buf ? SB1 : SB0);
        #pragma unroll
        for (int kk = 0; kk < 4; ++kk) {
            uint32_t a[2][4];
            #pragma unroll
            for (int mf = 0; mf < 2; ++mf) ldsm4(a[mf], aAddr[mf] + kk * 32);
            uint32_t b[2][4];
            ldsm4(b[0], bB + bOff[0] + kk * 32);
            ldsm4(b[1], bB + bOff[1] + kk * 32);
            #pragma unroll
            for (int mf = 0; mf < 2; ++mf) {
                hmma(acc[mf][0], a[mf], b[0][0], b[0][2]);
                hmma(acc[mf][1], a[mf], b[0][1], b[0][3]);
                hmma(acc[mf][2], a[mf], b[1][0], b[1][2]);
                hmma(acc[mf][3], a[mf], b[1][1], b[1][3]);
            }
        }
    };

    // --- prologue ---
    cpB(0, 0);
    cpB(1, 1);
    ldx(0);
    stx();
    cpwait<1>();          // B chunk 0 resident
    __syncthreads();

    // --- main loop ---
    for (int it = 0; it < NCH; ++it) {
        if (it + 1 < NCH) ldx(it + 1);      // LDGs issued under the MMAs
        mmaChunk(it & 1);
        __syncthreads();                     // reads of A / B[it] complete
        if (it + 1 < NCH) {
            stx();                           // A <- chunk it+1
            if (it + 2 < NCH) { cpB(it + 2, it & 1); cpwait<1>(); }
            else              { cpwait<0>(); }
            __syncthreads();                 // A + B[it+1] visible
        }
    }

    // --- epilogue ---
    float bias[4][2];
    {
        int c0 = warp_n * 32 + (lane & 3) * 2;
        #pragma unroll
        for (int nf = 0; nf < 4; ++nf) {
            bias[nf][0] = bkv[128 + c0 + nf * 8];
            bias[nf][1] = bkv[129 + c0 + nf * 8];
        }
    }
    __syncthreads();

    float* vsm = (float*)smem;
    {
        int r0 = warp_m * 32 + (lane >> 2);
        #pragma unroll
        for (int mf = 0; mf < 2; ++mf) {
            #pragma unroll
            for (int nf = 0; nf < 4; ++nf) {
                int r = r0 + mf * 16;
                int c = warp_n * 32 + nf * 8 + (lane & 3) * 2;
                vsm[r * V_STRIDE + c]           = acc[mf][nf][0] + bias[nf][0];
                vsm[r * V_STRIDE + c + 1]       = acc[mf][nf][1] + bias[nf][1];
                vsm[(r + 8) * V_STRIDE + c]     = acc[mf][nf][2] + bias[nf][0];
                vsm[(r + 8) * V_STRIDE + c + 1] = acc[mf][nf][3] + bias[nf][1];
            }
        }
    }
    __syncthreads();

    // Broadcast: each v row written 16x (one per head), fully coalesced.
    float* ob = out + (size_t)blockIdx.x * MTILE * 2048;
    for (int r = wid; r < MTILE; r += 8) {
        float4 val = *(const float4*)(vsm + r * V_STRIDE + lane * 4);
        float4* orow = (float4*)(ob + (size_t)r * 2048);
        #pragma unroll
        for (int h = 0; h < 16; ++h) orow[lane + h * 32] = val;
    }
}

// ---------------------------------------------------------------------------
extern "C" void kernel_launch(void* const* d_in, const int* in_sizes, int n_in,
                              void* d_out, int out_size) {
    const float* x   = (const float*)d_in[0];   // (4,4096,2048) fp32
    const float* Wkv = (const float*)d_in[3];   // (256,2048) fp32
    const float* bkv = (const float*)d_in[4];   // (256,) fp32
    float* out = (float*)d_out;                 // (4,4096,2048) fp32

    cudaFuncSetAttribute(mqa_gemm_kernel,
                         cudaFuncAttributeMaxDynamicSharedMemorySize, SMEM_TOTAL);

    convert_w_kernel<<<256, 256>>>(Wkv);
    mqa_gemm_kernel<<<16384 / MTILE, 256, SMEM_TOTAL>>>(x, bkv, out);
}

// round 4
// speedup vs baseline: 1.0945x; 1.0680x over previous
#include <cuda_runtime.h>
#include <cuda_fp16.h>
#include <cstdint>

// ============================================================================
// MQA_22436909154690 on GB300 (sm_103 base PTX target -> HMMA mma.sync path).
//
// Math: softmax over singleton axis == 1, so
//   out[b,l] = tile(v[b,l], H),  v = x @ Wv^T + bv,  Wv = Wkv[HD:2HD, :]
// => one GEMM [16384 x 2048] @ [2048 x 128] + bias + broadcast-x16 epilogue.
//
// R4 vs R3: single __syncthreads per K-chunk. A double-buffered in SMEM
// (LDG->STS gap covered by a full iteration), B triple-buffered via cp.async
// with prefetch distance 2. R3 ncu showed 2 barriers/iter + exposed LDG
// latency eating ~70% of each iteration (DRAM 45%, tensor 23%, issue 20%).
// ============================================================================

static constexpr int KDIM  = 2048;
static constexpr int MTILE = 64;
static constexpr int KC    = 64;            // K columns per chunk
static constexpr int NCH   = KDIM / KC;     // 32 chunks

// SMEM (bytes). 72 halves/row padding -> conflict-free ldmatrix.
static constexpr int SA0 = 0;                        // A buf0: [64][72] half
static constexpr int SA1 = 9216;                     // A buf1
static constexpr int SB  = 18432;                    // B bufs: 3 x [128][72] half
static constexpr int SBSZ = 18432;
static constexpr int SMEM_TOTAL = SB + 3 * SBSZ;     // 73728
static constexpr int V_STRIDE  = 132;                // epilogue overlay (33792 B)

// Pre-converted Wv in fp16, chunk-major: [chunk][n=128][k=64]
__device__ __align__(16) __half g_Wh[NCH * 128 * KC];

// ---------------------------------------------------------------------------
__device__ __forceinline__ uint32_t smem_u32(const void* p) {
    uint32_t a;
    asm("{ .reg .u64 t; cvta.to.shared.u64 t, %1; cvt.u32.u64 %0, t; }" : "=r"(a) : "l"(p));
    return a;
}
__device__ __forceinline__ void ldsm4(uint32_t* r, uint32_t addr) {
    asm volatile("ldmatrix.sync.aligned.m8n8.x4.shared.b16 {%0,%1,%2,%3}, [%4];"
                 : "=r"(r[0]), "=r"(r[1]), "=r"(r[2]), "=r"(r[3]) : "r"(addr));
}
__device__ __forceinline__ void hmma(float* d, const uint32_t* a, uint32_t b0, uint32_t b1) {
    asm volatile("mma.sync.aligned.m16n8k16.row.col.f32.f16.f16.f32 "
                 "{%0,%1,%2,%3}, {%4,%5,%6,%7}, {%8,%9}, {%0,%1,%2,%3};"
                 : "+f"(d[0]), "+f"(d[1]), "+f"(d[2]), "+f"(d[3])
                 : "r"(a[0]), "r"(a[1]), "r"(a[2]), "r"(a[3]), "r"(b0), "r"(b1));
}
template <int N>
__device__ __forceinline__ void cpwait() {
    asm volatile("cp.async.wait_group %0;" :: "n"(N) : "memory");
}
__device__ __forceinline__ uint32_t h2u(__half2 h) { return *reinterpret_cast<uint32_t*>(&h); }

// ---------------------------------------------------------------------------
__global__ void convert_w_kernel(const float* __restrict__ Wkv) {
    int idx = blockIdx.x * blockDim.x + threadIdx.x;  // 65536 threads, 4 halves
    int h4 = idx << 2;
    int c  = h4 >> 13;            // chunk
    int n  = (h4 >> 6) & 127;     // output column
    int k4 = h4 & 63;             // k within chunk
    float4 w = *(const float4*)(Wkv + (size_t)(128 + n) * KDIM + c * KC + k4);
    __half2 p0 = __float22half2_rn(make_float2(w.x, w.y));
    __half2 p1 = __float22half2_rn(make_float2(w.z, w.w));
    *(uint2*)(g_Wh + h4) = make_uint2(h2u(p0), h2u(p1));
}

// ---------------------------------------------------------------------------
// 256 CTAs x 256 threads, 2 CTAs/SM. 8 warps as 2(M) x 4(N): 32x32 frags.
// ---------------------------------------------------------------------------
__global__ void __launch_bounds__(256, 2)
mqa_gemm_kernel(const float* __restrict__ x, const float* __restrict__ bkv,
                float* __restrict__ out) {
    extern __shared__ char smem[];
    const uint32_t sb = smem_u32(smem);
    const int tid    = threadIdx.x;
    const int wid    = tid >> 5;
    const int lane   = tid & 31;
    const int warp_m = wid >> 2;
    const int warp_n = wid & 3;

    const float* xb = x + (size_t)blockIdx.x * MTILE * KDIM;

    // ldmatrix offsets (within an A / B buffer)
    uint32_t aOff[2];
    #pragma unroll
    for (int mf = 0; mf < 2; ++mf)
        aOff[mf] = (((warp_m * 32 + mf * 16 + (lane & 15)) * 72) << 1) + ((lane >> 4) << 4);
    uint32_t bOff[2];
    #pragma unroll
    for (int g = 0; g < 2; ++g)
        bOff[g] = (((warp_n * 32 + g * 16 + (lane & 15)) * 72) << 1) + ((lane >> 4) << 4);

    float acc[2][4][4];
    #pragma unroll
    for (int mf = 0; mf < 2; ++mf)
        #pragma unroll
        for (int nf = 0; nf < 4; ++nf)
            #pragma unroll
            for (int r = 0; r < 4; ++r) acc[mf][nf][r] = 0.f;

    float4 xs[2][2];                       // staged x chunk (next+1)
    const int f8a = tid;                   // 8-float unit indices for this thread
    const int f8b = tid + 256;

    auto ldx = [&](int ch) {
        const float* p0 = xb + (size_t)(f8a >> 3) * KDIM + ch * KC + ((f8a & 7) << 3);
        const float* p1 = xb + (size_t)(f8b >> 3) * KDIM + ch * KC + ((f8b & 7) << 3);
        xs[0][0] = ((const float4*)p0)[0];
        xs[0][1] = ((const float4*)p0)[1];
        xs[1][0] = ((const float4*)p1)[0];
        xs[1][1] = ((const float4*)p1)[1];
    };
    auto stx = [&](int buf) {
        uint32_t base = (buf ? SA1 : SA0);
        #pragma unroll
        for (int i = 0; i < 2; ++i) {
            int f8 = (i ? f8b : f8a);
            __half2 h0 = __float22half2_rn(make_float2(xs[i][0].x, xs[i][0].y));
            __half2 h1 = __float22half2_rn(make_float2(xs[i][0].z, xs[i][0].w));
            __half2 h2 = __float22half2_rn(make_float2(xs[i][1].x, xs[i][1].y));
            __half2 h3 = __float22half2_rn(make_float2(xs[i][1].z, xs[i][1].w));
            uint4 v = make_uint4(h2u(h0), h2u(h1), h2u(h2), h2u(h3));
            *(uint4*)(smem + base + (((f8 >> 3) * 72 + ((f8 & 7) << 3)) << 1)) = v;
        }
    };
    auto cpB = [&](int ch, int buf) {
        const __half* src = g_Wh + (size_t)ch * (128 * KC);
        uint32_t dbase = sb + SB + buf * SBSZ;
        #pragma unroll
        for (int j = 0; j < 4; ++j) {
            int idx = tid + j * 256;
            int n = idx >> 3, seg = idx & 7;
            uint32_t dst = dbase + ((n * 72 + seg * 8) << 1);
            const void* s = src + n * KC + seg * 8;
            asm volatile("cp.async.cg.shared.global [%0], [%1], 16;"
                         :: "r"(dst), "l"(s) : "memory");
        }
        asm volatile("cp.async.commit_group;" ::: "memory");
    };
    auto mmaChunk = [&](int abuf, int bbuf) {
        uint32_t bA = sb + (abuf ? SA1 : SA0);
        uint32_t bB = sb + SB + bbuf * SBSZ;
        #pragma unroll
        for (int kk = 0; kk < 4; ++kk) {
            uint32_t a[2][4];
            ldsm4(a[0], bA + aOff[0] + kk * 32);
            ldsm4(a[1], bA + aOff[1] + kk * 32);
            uint32_t b[2][4];
            ldsm4(b[0], bB + bOff[0] + kk * 32);
            ldsm4(b[1], bB + bOff[1] + kk * 32);
            #pragma unroll
            for (int mf = 0; mf < 2; ++mf) {
                hmma(acc[mf][0], a[mf], b[0][0], b[0][2]);
                hmma(acc[mf][1], a[mf], b[0][1], b[0][3]);
                hmma(acc[mf][2], a[mf], b[1][0], b[1][2]);
                hmma(acc[mf][3], a[mf], b[1][1], b[1][3]);
            }
        }
    };

    // --- prologue: B chunks 0,1 in flight; A chunk 0 stored; chunk 1 staged ---
    cpB(0, 0);
    cpB(1, 1);
    ldx(0);
    stx(0);                 // one-time exposed LDG latency
    ldx(1);
    cpwait<1>();            // B chunk 0 resident
    __syncthreads();

    // --- main loop: ONE barrier per chunk ---
    for (int it = 0; it < NCH; ++it) {
        // entering: A[it&1] + B[it%3] ready; xs holds chunk it+1 (in flight)
        if (it + 1 < NCH) stx((it + 1) & 1);        // LDGs had a full iter to land
        if (it + 2 < NCH) { ldx(it + 2); cpB(it + 2, (it + 2) % 3); }
        mmaChunk(it & 1, it % 3);
        if (it + 2 < NCH) cpwait<1>();              // B[it+1] done
        else              cpwait<0>();
        __syncthreads();                            // publishes A[(it+1)&1], B[it+1]
    }

    // --- epilogue ---
    float bias[4][2];
    {
        int c0 = warp_n * 32 + (lane & 3) * 2;
        #pragma unroll
        for (int nf = 0; nf < 4; ++nf) {
            bias[nf][0] = bkv[128 + c0 + nf * 8];
            bias[nf][1] = bkv[129 + c0 + nf * 8];
        }
    }
    __syncthreads();

    float* vsm = (float*)smem;
    {
        int r0 = warp_m * 32 + (lane >> 2);
        #pragma unroll
        for (int mf = 0; mf < 2; ++mf) {
            #pragma unroll
            for (int nf = 0; nf < 4; ++nf) {
                int r = r0 + mf * 16;
                int c = warp_n * 32 + nf * 8 + (lane & 3) * 2;
                vsm[r * V_STRIDE + c]           = acc[mf][nf][0] + bias[nf][0];
                vsm[r * V_STRIDE + c + 1]       = acc[mf][nf][1] + bias[nf][1];
                vsm[(r + 8) * V_STRIDE + c]     = acc[mf][nf][2] + bias[nf][0];
                vsm[(r + 8) * V_STRIDE + c + 1] = acc[mf][nf][3] + bias[nf][1];
            }
        }
    }
    __syncthreads();

    // Broadcast: each v row written 16x (one per head), fully coalesced.
    float* ob = out + (size_t)blockIdx.x * MTILE * 2048;
    for (int r = wid; r < MTILE; r += 8) {
        float4 val = *(const float4*)(vsm + r * V_STRIDE + lane * 4);
        float4* orow = (float4*)(ob + (size_t)r * 2048);
        #pragma unroll
        for (int h = 0; h < 16; ++h) orow[lane + h * 32] = val;
    }
}

// ---------------------------------------------------------------------------
extern "C" void kernel_launch(void* const* d_in, const int* in_sizes, int n_in,
                              void* d_out, int out_size) {
    const float* x   = (const float*)d_in[0];   // (4,4096,2048) fp32
    const float* Wkv = (const float*)d_in[3];   // (256,2048) fp32
    const float* bkv = (const float*)d_in[4];   // (256,) fp32
    float* out = (float*)d_out;                 // (4,4096,2048) fp32

    cudaFuncSetAttribute(mqa_gemm_kernel,
                         cudaFuncAttributeMaxDynamicSharedMemorySize, SMEM_TOTAL);

    convert_w_kernel<<<256, 256>>>(Wkv);
    mqa_gemm_kernel<<<16384 / MTILE, 256, SMEM_TOTAL>>>(x, bkv, out);
}